// round 15
// baseline (speedup 1.0000x reference)
#include <cuda_runtime.h>
#include <math.h>

// x (64, 40, 64, 500) f32 -> per (b,f): cov 64x64, eigh (parallel Jacobi), logm, triu -> (64,40,2080)
// One block per matrix. Jacobi loop = R13 winner (bank-balanced pairs, float4 params,
// merged A+V update). This round: transposed float4-tiled covariance (LDS.128 gram
// loads, 4x fewer cov wavefronts), gmem rowsum pre-pass, outer-product reconstruction
// without W materialization. NSWEEPS=6 is the convergence floor.

#define C 64
#define TLEN 500
#define NMAT 2560
#define NTRI 2080
#define LDA 65          // stride for sA  (65 % 32 == 1)
#define LDV 66          // stride for sVt (even -> float2-aligned rows)
#define XT_STRIDE 68    // cov tile stride in floats (17 float4s)
#define NSWEEPS 6
#define THREADS 256

// Bank-balanced (p,q) labels per round: p | (q<<8)
__device__ int g_pq[63 * 32];

__global__ void prep_pairs_kernel()
{
    int r = threadIdx.x;
    if (r >= 63) return;

    int A[32], B[32];
    A[0] = 63; B[0] = r % 63;
    for (int t = 1; t < 32; t++) {
        A[t] = (r + t) % 63;
        B[t] = (r - t + 63) % 63;
    }
    int inc[32][2];
    int cnt[32];
    for (int v = 0; v < 32; v++) cnt[v] = 0;
    for (int k = 0; k < 32; k++) {
        int u = A[k] & 31, v = B[k] & 31;
        inc[u][cnt[u]++] = k;
        inc[v][cnt[v]++] = k;
    }
    bool done[32];
    for (int k = 0; k < 32; k++) done[k] = false;
    for (int k0 = 0; k0 < 32; k0++) {
        if (done[k0]) continue;
        int e = k0;
        int u = A[e] & 31;
        while (!done[e]) {
            done[e] = true;
            int p, q;
            if ((A[e] & 31) == u) { p = A[e]; q = B[e]; }
            else                  { p = B[e]; q = A[e]; }
            g_pq[r * 32 + e] = p | (q << 8);
            int v = q & 31;
            int e2 = (inc[v][0] == e) ? inc[v][1] : inc[v][0];
            e = e2;
            u = v;
        }
    }
}

__global__ __launch_bounds__(THREADS, 5)
void spd_logm_kernel(const float* __restrict__ xin, float* __restrict__ out)
{
    // pool: sA [0,4160) | sVt [4160, 8384). cov tile xt aliases pool[0,4352)
    // (dead before sA/sVt are first written).
    __shared__ __align__(16) float pool[4160 + 4224];
    __shared__ float4 sprm[32];           // (c, s, p, q) per pair
    __shared__ int    s_pqtab[63 * 32];   // staged pair schedule
    __shared__ float  ssum4[256];         // rowsum partials
    __shared__ float  ssum[C];
    __shared__ float  slam[C];

    float* sA  = pool;
    float* sVt = pool + 4160;
    float*  xt  = pool;
    float4* xt4 = (float4*)pool;

    const int tid = threadIdx.x;
    const int lane = tid & 31;
    const int w8 = tid >> 5;
    const int mat = blockIdx.x;
    const float* __restrict__ xm = xin + (size_t)mat * (C * TLEN);
    float* __restrict__ om = out + (size_t)mat * NTRI;

    // stage pair schedule into shared
#pragma unroll
    for (int it = 0; it < 8; it++) {
        int e = tid + it * THREADS;
        if (e < 63 * 32) s_pqtab[e] = g_pq[e];
    }

    // ---------------- Phase 0: row sums (gmem pre-pass; DRAM is idle) ----------------
    {
        int row = tid & 63, q = tid >> 6;        // 4 quarters of 125
        const float* xr = xm + row * TLEN + q * 125;
        float s = 0.0f;
#pragma unroll 5
        for (int k = 0; k < 125; k++) s += xr[k];
        ssum4[tid] = s;
    }
    __syncthreads();
    if (tid < C)
        ssum[tid] = ssum4[tid] + ssum4[tid + 64] + ssum4[tid + 128] + ssum4[tid + 192];

    // ---------------- Phase 1: covariance (transposed float4 tiles) ----------------
    {
        const int ty = tid >> 4;        // 0..15 -> rows 4ty..4ty+3
        const int tx = tid & 15;        // 0..15 -> cols 4tx..4tx+3
        float acc[4][4];
#pragma unroll
        for (int i = 0; i < 4; i++)
#pragma unroll
            for (int j = 0; j < 4; j++) acc[i][j] = 0.0f;

        for (int tile = 0; tile < 8; tile++) {
            int t0 = tile * 64;
            __syncthreads();            // protect xt from previous tile's readers
            // load tile t-major: xt[tt*68 + r]
#pragma unroll
            for (int it = 0; it < 16; it++) {
                int e = tid + it * THREADS;     // 0..4095
                int r = e >> 6, tt = e & 63;
                int t = t0 + tt;
                xt[tt * XT_STRIDE + r] = (t < TLEN) ? xm[r * TLEN + t] : 0.0f;
            }
            __syncthreads();
#pragma unroll 8
            for (int tt = 0; tt < 64; tt++) {
                float4 Av = xt4[tt * 17 + ty];
                float4 Bv = xt4[tt * 17 + tx];
                acc[0][0] += Av.x * Bv.x; acc[0][1] += Av.x * Bv.y; acc[0][2] += Av.x * Bv.z; acc[0][3] += Av.x * Bv.w;
                acc[1][0] += Av.y * Bv.x; acc[1][1] += Av.y * Bv.y; acc[1][2] += Av.y * Bv.z; acc[1][3] += Av.y * Bv.w;
                acc[2][0] += Av.z * Bv.x; acc[2][1] += Av.z * Bv.y; acc[2][2] += Av.z * Bv.z; acc[2][3] += Av.z * Bv.w;
                acc[3][0] += Av.w * Bv.x; acc[3][1] += Av.w * Bv.y; acc[3][2] += Av.w * Bv.z; acc[3][3] += Av.w * Bv.w;
            }
        }
        __syncthreads();                // xt dead; pool becomes sA/sVt

        const float invT  = 1.0f / (float)TLEN;
        const float invT1 = 1.0f / (float)(TLEN - 1);
#pragma unroll
        for (int i = 0; i < 4; i++) {
            float si = ssum[4 * ty + i];
#pragma unroll
            for (int j = 0; j < 4; j++) {
                float sj = ssum[4 * tx + j];
                sA[(4 * ty + i) * LDA + (4 * tx + j)] =
                    (acc[i][j] - si * sj * invT) * invT1;
            }
        }
    }

    // Vt = I
#pragma unroll
    for (int it = 0; it < 16; it++) {
        int e = tid + it * THREADS;
        int i = e >> 6, j = e & 63;
        sVt[i * LDV + j] = (i == j) ? 1.0f : 0.0f;
    }
    __syncthreads();

    // ---------------- Phase 2: parallel cyclic Jacobi ----------------
    for (int sweep = 0; sweep < NSWEEPS; sweep++) {
        for (int r = 0; r < 63; r++) {
            if (tid < 32) {
                int pqt = s_pqtab[r * 32 + tid];
                int p = pqt & 255, q = pqt >> 8;
                float app = sA[p * LDA + p];
                float aqq = sA[q * LDA + q];
                float apq = sA[p * LDA + q];
                float cc, ss;
                if (fabsf(apq) > 1e-36f) {
                    float theta = (aqq - app) / (2.0f * apq);
                    float t = copysignf(1.0f, theta) /
                              (fabsf(theta) + sqrtf(theta * theta + 1.0f));
                    cc = rsqrtf(t * t + 1.0f);
                    ss = t * cc;
                } else { cc = 1.0f; ss = 0.0f; }
                sprm[tid] = make_float4(cc, ss,
                                        __int_as_float(p), __int_as_float(q));
            }
            __syncthreads();

            // Merged A + V update (conflict-free: {p mod 32}, {q mod 32} are permutations)
            {
                const float4 P2 = sprm[lane];
                const int p2 = __float_as_int(P2.z), q2 = __float_as_int(P2.w);
#pragma unroll
                for (int it = 0; it < 4; it++) {
                    const float4 P1 = sprm[w8 + it * 8];   // broadcast
                    const int p1 = __float_as_int(P1.z), q1 = __float_as_int(P1.w);

                    float a00 = sA[p1 * LDA + p2], a01 = sA[p1 * LDA + q2];
                    float a10 = sA[q1 * LDA + p2], a11 = sA[q1 * LDA + q2];
                    float t00 = P1.x * a00 - P1.y * a10, t01 = P1.x * a01 - P1.y * a11;
                    float t10 = P1.y * a00 + P1.x * a10, t11 = P1.y * a01 + P1.x * a11;
                    sA[p1 * LDA + p2] = P2.x * t00 - P2.y * t01;
                    sA[p1 * LDA + q2] = P2.y * t00 + P2.x * t01;
                    sA[q1 * LDA + p2] = P2.x * t10 - P2.y * t11;
                    sA[q1 * LDA + q2] = P2.y * t10 + P2.x * t11;

                    float2* vp2 = (float2*)&sVt[p1 * LDV];
                    float2* vq2 = (float2*)&sVt[q1 * LDV];
                    float2 vp = vp2[lane], vq = vq2[lane];
                    float2 np, nq;
                    np.x = P1.x * vp.x - P1.y * vq.x;
                    np.y = P1.x * vp.y - P1.y * vq.y;
                    nq.x = P1.y * vp.x + P1.x * vq.x;
                    nq.y = P1.y * vp.y + P1.x * vq.y;
                    vp2[lane] = np;
                    vq2[lane] = nq;
                }
            }
            __syncthreads();
        }
    }

    // ---------------- Phase 3: log-eigenvalues + outer-product reconstruction ----------------
    if (tid < C) {
        float lam = sA[tid * LDA + tid];
        lam = fmaxf(lam, 1e-10f);
        slam[tid] = logf(lam);
    }
    __syncthreads();

    // logm[i][j] = sum_e log(lam[e]) * Vt[e][i] * Vt[e][j]
    // warp w owns i-strip [8w, 8w+8); j = jh*32 + lane
    {
        const int i0 = w8 * 8;
        float acc[8][2];
#pragma unroll
        for (int ii = 0; ii < 8; ii++) { acc[ii][0] = 0.0f; acc[ii][1] = 0.0f; }

#pragma unroll 4
        for (int e = 0; e < C; e++) {
            float le = slam[e];
            float vj0 = sVt[e * LDV + lane];
            float vj1 = sVt[e * LDV + 32 + lane];
#pragma unroll
            for (int ii = 0; ii < 8; ii++) {
                float wei = sVt[e * LDV + i0 + ii] * le;   // broadcast
                acc[ii][0] += wei * vj0;
                acc[ii][1] += wei * vj1;
            }
        }
#pragma unroll
        for (int ii = 0; ii < 8; ii++) {
            int i = i0 + ii;
            int base = i * C - ((i * (i - 1)) >> 1) - i;
#pragma unroll
            for (int jh = 0; jh < 2; jh++) {
                int j = jh * 32 + lane;
                if (i <= j) om[base + j] = acc[ii][jh];
            }
        }
    }
}

extern "C" void kernel_launch(void* const* d_in, const int* in_sizes, int n_in,
                              void* d_out, int out_size)
{
    const float* x = (const float*)d_in[0];
    float* out = (float*)d_out;
    prep_pairs_kernel<<<1, 64>>>();
    spd_logm_kernel<<<NMAT, THREADS>>>(x, out);
}

// round 16
// speedup vs baseline: 1.0981x; 1.0981x over previous
#include <cuda_runtime.h>
#include <math.h>

// x (64, 40, 64, 500) f32 -> per (b,f): cov 64x64, eigh (parallel Jacobi), logm, triu -> (64,40,2080)
// One block per matrix. Jacobi loop = R13 winner (bank-balanced pairs, float4 params,
// merged A+V update). Cov: transposed float4 tiles (LDS.128 gram loads). Rowsum:
// warp-per-row coalesced gmem pass + shfl reduction (R14's uncoalesced version caused
// the regression). Recon: outer-product, no W materialization. NSWEEPS=6 floor.

#define C 64
#define TLEN 500
#define NMAT 2560
#define NTRI 2080
#define LDA 65          // stride for sA  (65 % 32 == 1)
#define LDV 66          // stride for sVt (even -> float2-aligned rows)
#define XT_STRIDE 68    // cov tile stride in floats (17 float4s)
#define NSWEEPS 6
#define THREADS 256

// Bank-balanced (p,q) labels per round: p | (q<<8)
__device__ int g_pq[63 * 32];

__global__ void prep_pairs_kernel()
{
    int r = threadIdx.x;
    if (r >= 63) return;

    int A[32], B[32];
    A[0] = 63; B[0] = r % 63;
    for (int t = 1; t < 32; t++) {
        A[t] = (r + t) % 63;
        B[t] = (r - t + 63) % 63;
    }
    int inc[32][2];
    int cnt[32];
    for (int v = 0; v < 32; v++) cnt[v] = 0;
    for (int k = 0; k < 32; k++) {
        int u = A[k] & 31, v = B[k] & 31;
        inc[u][cnt[u]++] = k;
        inc[v][cnt[v]++] = k;
    }
    bool done[32];
    for (int k = 0; k < 32; k++) done[k] = false;
    for (int k0 = 0; k0 < 32; k0++) {
        if (done[k0]) continue;
        int e = k0;
        int u = A[e] & 31;
        while (!done[e]) {
            done[e] = true;
            int p, q;
            if ((A[e] & 31) == u) { p = A[e]; q = B[e]; }
            else                  { p = B[e]; q = A[e]; }
            g_pq[r * 32 + e] = p | (q << 8);
            int v = q & 31;
            int e2 = (inc[v][0] == e) ? inc[v][1] : inc[v][0];
            e = e2;
            u = v;
        }
    }
}

__global__ __launch_bounds__(THREADS, 5)
void spd_logm_kernel(const float* __restrict__ xin, float* __restrict__ out)
{
    // pool: sA [0,4160) | sVt [4160, 8384). cov tile xt aliases pool[0,4352)
    __shared__ __align__(16) float pool[4160 + 4224];
    __shared__ float4 sprm[32];           // (c, s, p, q) per pair
    __shared__ int    s_pqtab[63 * 32];   // staged pair schedule
    __shared__ float  ssum[C];
    __shared__ float  slam[C];

    float* sA  = pool;
    float* sVt = pool + 4160;
    float*  xt  = pool;
    float4* xt4 = (float4*)pool;

    const int tid = threadIdx.x;
    const int lane = tid & 31;
    const int w8 = tid >> 5;
    const int mat = blockIdx.x;
    const float* __restrict__ xm = xin + (size_t)mat * (C * TLEN);
    float* __restrict__ om = out + (size_t)mat * NTRI;

    // stage pair schedule into shared
#pragma unroll
    for (int it = 0; it < 8; it++) {
        int e = tid + it * THREADS;
        if (e < 63 * 32) s_pqtab[e] = g_pq[e];
    }

    // ---------------- Phase 0: row sums (coalesced warp-per-row + shfl) ----------------
    {
#pragma unroll
        for (int rr = 0; rr < 8; rr++) {
            int row = w8 * 8 + rr;
            const float* xr = xm + row * TLEN;
            float s = 0.0f;
#pragma unroll
            for (int t = lane; t < TLEN; t += 32) s += xr[t];
#pragma unroll
            for (int o = 16; o > 0; o >>= 1) s += __shfl_xor_sync(0xffffffffu, s, o);
            if (lane == 0) ssum[row] = s;
        }
    }

    // ---------------- Phase 1: covariance (transposed float4 tiles) ----------------
    {
        const int ty = tid >> 4;        // 0..15 -> rows 4ty..4ty+3
        const int tx = tid & 15;        // 0..15 -> cols 4tx..4tx+3
        float acc[4][4];
#pragma unroll
        for (int i = 0; i < 4; i++)
#pragma unroll
            for (int j = 0; j < 4; j++) acc[i][j] = 0.0f;

        for (int tile = 0; tile < 8; tile++) {
            int t0 = tile * 64;
            __syncthreads();            // protect xt from previous tile's readers
            // load tile t-major: xt[tt*68 + r]
#pragma unroll
            for (int it = 0; it < 16; it++) {
                int e = tid + it * THREADS;     // 0..4095
                int r = e >> 6, tt = e & 63;
                int t = t0 + tt;
                xt[tt * XT_STRIDE + r] = (t < TLEN) ? xm[r * TLEN + t] : 0.0f;
            }
            __syncthreads();
#pragma unroll 8
            for (int tt = 0; tt < 64; tt++) {
                float4 Av = xt4[tt * 17 + ty];
                float4 Bv = xt4[tt * 17 + tx];
                acc[0][0] += Av.x * Bv.x; acc[0][1] += Av.x * Bv.y; acc[0][2] += Av.x * Bv.z; acc[0][3] += Av.x * Bv.w;
                acc[1][0] += Av.y * Bv.x; acc[1][1] += Av.y * Bv.y; acc[1][2] += Av.y * Bv.z; acc[1][3] += Av.y * Bv.w;
                acc[2][0] += Av.z * Bv.x; acc[2][1] += Av.z * Bv.y; acc[2][2] += Av.z * Bv.z; acc[2][3] += Av.z * Bv.w;
                acc[3][0] += Av.w * Bv.x; acc[3][1] += Av.w * Bv.y; acc[3][2] += Av.w * Bv.z; acc[3][3] += Av.w * Bv.w;
            }
        }
        __syncthreads();                // xt dead; pool becomes sA/sVt

        const float invT  = 1.0f / (float)TLEN;
        const float invT1 = 1.0f / (float)(TLEN - 1);
#pragma unroll
        for (int i = 0; i < 4; i++) {
            float si = ssum[4 * ty + i];
#pragma unroll
            for (int j = 0; j < 4; j++) {
                float sj = ssum[4 * tx + j];
                sA[(4 * ty + i) * LDA + (4 * tx + j)] =
                    (acc[i][j] - si * sj * invT) * invT1;
            }
        }
    }

    // Vt = I
#pragma unroll
    for (int it = 0; it < 16; it++) {
        int e = tid + it * THREADS;
        int i = e >> 6, j = e & 63;
        sVt[i * LDV + j] = (i == j) ? 1.0f : 0.0f;
    }
    __syncthreads();

    // ---------------- Phase 2: parallel cyclic Jacobi ----------------
    for (int sweep = 0; sweep < NSWEEPS; sweep++) {
        for (int r = 0; r < 63; r++) {
            if (tid < 32) {
                int pqt = s_pqtab[r * 32 + tid];
                int p = pqt & 255, q = pqt >> 8;
                float app = sA[p * LDA + p];
                float aqq = sA[q * LDA + q];
                float apq = sA[p * LDA + q];
                float cc, ss;
                if (fabsf(apq) > 1e-36f) {
                    float theta = (aqq - app) / (2.0f * apq);
                    float t = copysignf(1.0f, theta) /
                              (fabsf(theta) + sqrtf(theta * theta + 1.0f));
                    cc = rsqrtf(t * t + 1.0f);
                    ss = t * cc;
                } else { cc = 1.0f; ss = 0.0f; }
                sprm[tid] = make_float4(cc, ss,
                                        __int_as_float(p), __int_as_float(q));
            }
            __syncthreads();

            // Merged A + V update (conflict-free: {p mod 32}, {q mod 32} are permutations)
            {
                const float4 P2 = sprm[lane];
                const int p2 = __float_as_int(P2.z), q2 = __float_as_int(P2.w);
#pragma unroll
                for (int it = 0; it < 4; it++) {
                    const float4 P1 = sprm[w8 + it * 8];   // broadcast
                    const int p1 = __float_as_int(P1.z), q1 = __float_as_int(P1.w);

                    float a00 = sA[p1 * LDA + p2], a01 = sA[p1 * LDA + q2];
                    float a10 = sA[q1 * LDA + p2], a11 = sA[q1 * LDA + q2];
                    float t00 = P1.x * a00 - P1.y * a10, t01 = P1.x * a01 - P1.y * a11;
                    float t10 = P1.y * a00 + P1.x * a10, t11 = P1.y * a01 + P1.x * a11;
                    sA[p1 * LDA + p2] = P2.x * t00 - P2.y * t01;
                    sA[p1 * LDA + q2] = P2.y * t00 + P2.x * t01;
                    sA[q1 * LDA + p2] = P2.x * t10 - P2.y * t11;
                    sA[q1 * LDA + q2] = P2.y * t10 + P2.x * t11;

                    float2* vp2 = (float2*)&sVt[p1 * LDV];
                    float2* vq2 = (float2*)&sVt[q1 * LDV];
                    float2 vp = vp2[lane], vq = vq2[lane];
                    float2 np, nq;
                    np.x = P1.x * vp.x - P1.y * vq.x;
                    np.y = P1.x * vp.y - P1.y * vq.y;
                    nq.x = P1.y * vp.x + P1.x * vq.x;
                    nq.y = P1.y * vp.y + P1.x * vq.y;
                    vp2[lane] = np;
                    vq2[lane] = nq;
                }
            }
            __syncthreads();
        }
    }

    // ---------------- Phase 3: log-eigenvalues + outer-product reconstruction ----------------
    if (tid < C) {
        float lam = sA[tid * LDA + tid];
        lam = fmaxf(lam, 1e-10f);
        slam[tid] = logf(lam);
    }
    __syncthreads();

    // logm[i][j] = sum_e log(lam[e]) * Vt[e][i] * Vt[e][j]
    // warp w owns i-strip [8w, 8w+8); j = jh*32 + lane
    {
        const int i0 = w8 * 8;
        float acc[8][2];
#pragma unroll
        for (int ii = 0; ii < 8; ii++) { acc[ii][0] = 0.0f; acc[ii][1] = 0.0f; }

#pragma unroll 4
        for (int e = 0; e < C; e++) {
            float le = slam[e];
            float vj0 = sVt[e * LDV + lane];
            float vj1 = sVt[e * LDV + 32 + lane];
#pragma unroll
            for (int ii = 0; ii < 8; ii++) {
                float wei = sVt[e * LDV + i0 + ii] * le;   // broadcast
                acc[ii][0] += wei * vj0;
                acc[ii][1] += wei * vj1;
            }
        }
#pragma unroll
        for (int ii = 0; ii < 8; ii++) {
            int i = i0 + ii;
            int base = i * C - ((i * (i - 1)) >> 1) - i;
#pragma unroll
            for (int jh = 0; jh < 2; jh++) {
                int j = jh * 32 + lane;
                if (i <= j) om[base + j] = acc[ii][jh];
            }
        }
    }
}

extern "C" void kernel_launch(void* const* d_in, const int* in_sizes, int n_in,
                              void* d_out, int out_size)
{
    const float* x = (const float*)d_in[0];
    float* out = (float*)d_out;
    prep_pairs_kernel<<<1, 64>>>();
    spd_logm_kernel<<<NMAT, THREADS>>>(x, out);
}